// round 6
// baseline (speedup 1.0000x reference)
#include <cuda_runtime.h>

// Problem constants: infer/ref shape (2,7,7,3,256,256) -> N=98 images, C=3, H=W=256
#define NIMG   98
#define HH     256
#define WW     256
#define ROWS_PER_BLK 32
#define TILES_PER_IMG (HH / ROWS_PER_BLK)   // 8
#define NBLOCKS (NIMG * TILES_PER_IMG)      // 784
#define CH_STRIDE (HH * WW)                 // 65536 floats per channel
#define IMG_STRIDE (3 * CH_STRIDE)          // per image

__device__ float g_partials[NBLOCKS];
__device__ unsigned int g_count;            // zero-init; self-resetting each run

__global__ __launch_bounds__(256, 4)
void detail_loss_main(const float* __restrict__ infer, const float* __restrict__ ref,
                      float* __restrict__ out)
{
    __shared__ float tile[ROWS_PER_BLK + 2][WW];   // 34 x 256 floats = 34 KB
    __shared__ float red[256];
    __shared__ int   is_last;

    const int tid = threadIdx.x;
    const int blk = blockIdx.x;
    const int n   = blk >> 3;        // image index
    const int t   = blk & 7;         // row-tile index
    const int h0  = t * ROWS_PER_BLK;

    const size_t base = (size_t)n * IMG_STRIDE;
    const float4* __restrict__ A = (const float4*)(infer + base);
    const float4* __restrict__ B = (const float4*)(ref   + base);
    const int CS4 = CH_STRIDE / 4;   // 16384 float4 per channel
    const int W4  = WW / 4;          // 64

    // ---- Interior load: 32 rows x 64 float4 = 2048 units, exactly 8 per thread.
    // No boundary predicates -> ptxas can batch loads across unrolled iterations
    // for high MLP.
    #pragma unroll 4
    for (int k = 0; k < 8; k++) {
        const int idx = tid + 256 * k;
        const int r   = idx >> 6;        // 0..31 (interior row within tile)
        const int c4  = idx & 63;
        const int off = (h0 + r) * W4 + c4;
        float4 a0 = A[off];
        float4 b0 = B[off];
        float4 a1 = A[off + CS4];
        float4 b1 = B[off + CS4];
        float4 a2 = A[off + 2 * CS4];
        float4 b2 = B[off + 2 * CS4];
        float4 d;
        d.x = (a0.x - b0.x) + (a1.x - b1.x) + (a2.x - b2.x);
        d.y = (a0.y - b0.y) + (a1.y - b1.y) + (a2.y - b2.y);
        d.z = (a0.z - b0.z) + (a1.z - b1.z) + (a2.z - b2.z);
        d.w = (a0.w - b0.w) + (a1.w - b1.w) + (a2.w - b2.w);
        *(float4*)&tile[r + 1][c4 * 4] = d;
    }

    // ---- Halo rows: tile row 0 (gh = h0-1) and row 33 (gh = h0+32).
    // 128 units, threads 0..127 take one each.
    if (tid < 2 * W4) {
        const int r  = (tid < W4) ? 0 : (ROWS_PER_BLK + 1);
        const int c4 = tid & (W4 - 1);
        const int gh = h0 - 1 + ((tid < W4) ? 0 : (ROWS_PER_BLK + 1));
        float4 d = make_float4(0.f, 0.f, 0.f, 0.f);
        if ((unsigned)gh < (unsigned)HH) {
            const int off = gh * W4 + c4;
            float4 a0 = A[off];
            float4 b0 = B[off];
            float4 a1 = A[off + CS4];
            float4 b1 = B[off + CS4];
            float4 a2 = A[off + 2 * CS4];
            float4 b2 = B[off + 2 * CS4];
            d.x = (a0.x - b0.x) + (a1.x - b1.x) + (a2.x - b2.x);
            d.y = (a0.y - b0.y) + (a1.y - b1.y) + (a2.y - b2.y);
            d.z = (a0.z - b0.z) + (a1.z - b1.z) + (a2.z - b2.z);
            d.w = (a0.w - b0.w) + (a1.w - b1.w) + (a2.w - b2.w);
        }
        *(float4*)&tile[r][c4 * 4] = d;
    }
    __syncthreads();

    // ---- Compute phase: each thread owns one column, rolling vertical window.
    const int w = tid;                     // 0..255
    const bool has_l = (w > 0);
    const bool has_r = (w < WW - 1);
    float vm = tile[0][w];                 // row r-1 for r=1
    float vc = tile[1][w];
    float acc = 0.f;
    #pragma unroll 8
    for (int r = 1; r <= ROWS_PER_BLK; r++) {
        const float vp = tile[r + 1][w];
        const float dl = has_l ? tile[r][w - 1] : 0.f;
        const float dr = has_r ? tile[r][w + 1] : 0.f;
        acc += fabsf(dr - dl) + fabsf(vp - vm);
        vm = vc;
        vc = vp;
    }

    // ---- Block reduction ----
    red[tid] = acc;
    __syncthreads();
    #pragma unroll
    for (int s = 128; s > 0; s >>= 1) {
        if (tid < s) red[tid] += red[tid + s];
        __syncthreads();
    }
    if (tid == 0) g_partials[blk] = red[0];

    // ---- Last-block final reduction (fused; no second launch) ----
    if (tid == 0) {
        __threadfence();
        unsigned old = atomicAdd(&g_count, 1u);
        is_last = (old == NBLOCKS - 1);
        if (is_last) g_count = 0;          // reset for next graph replay
    }
    __syncthreads();
    if (is_last) {
        __threadfence();                    // acquire all blocks' partial writes
        float s = 0.f;
        for (int i = tid; i < NBLOCKS; i += 256) s += g_partials[i];
        red[tid] = s;
        __syncthreads();
        #pragma unroll
        for (int k = 128; k > 0; k >>= 1) {
            if (tid < k) red[tid] += red[tid + k];
            __syncthreads();
        }
        if (tid == 0) {
            // result = A / (4 * 98 * 258 * 256): 0.5 grad coeff folded out of
            // both |.| sums, /2 average of the two losses, mean denominators
            // 98*258*256 for each term.
            out[0] = red[0] * (1.0f / 25890816.0f);
        }
    }
}

extern "C" void kernel_launch(void* const* d_in, const int* in_sizes, int n_in,
                              void* d_out, int out_size)
{
    const float* infer = (const float*)d_in[0];
    const float* ref   = (const float*)d_in[1];
    float* out = (float*)d_out;
    (void)in_sizes; (void)n_in; (void)out_size;

    detail_loss_main<<<NBLOCKS, 256>>>(infer, ref, out);
}

// round 7
// speedup vs baseline: 1.2282x; 1.2282x over previous
#include <cuda_runtime.h>

// infer/ref shape (2,7,7,3,256,256) -> N=98 images, C=3, H=W=256
#define NIMG   98
#define HH     256
#define WW     256
#define STRIP  16                            // rows per warp-task
#define NSTRIP (HH / STRIP)                  // 16
#define NTASK  (NIMG * NSTRIP)               // 1568
#define CH_STRIDE (HH * WW)                  // 65536 floats per channel
#define IMG_STRIDE (3 * CH_STRIDE)
#define CS4 (CH_STRIDE / 4)                  // 16384 float4 per channel
#define W4  (WW / 4)                         // 64 float4 per row

__device__ float g_partials[NTASK];
__device__ unsigned int g_count;             // zero-init; self-resets each run

// Load one row's D = sum_c(infer - ref) for this lane's 8 columns.
// Returns zeros for out-of-image rows (vertical zero padding).
static __device__ __forceinline__ void load_row(
    const float4* __restrict__ A, const float4* __restrict__ B,
    int gh, int lane, float4& x, float4& y)
{
    x = make_float4(0.f, 0.f, 0.f, 0.f);
    y = make_float4(0.f, 0.f, 0.f, 0.f);
    if ((unsigned)gh < (unsigned)HH) {
        const int off = gh * W4 + 2 * lane;
        // 12 independent LDG.128
        float4 a0 = A[off];            float4 b0 = B[off];
        float4 a1 = A[off + CS4];      float4 b1 = B[off + CS4];
        float4 a2 = A[off + 2*CS4];    float4 b2 = B[off + 2*CS4];
        float4 c0 = A[off + 1];        float4 e0 = B[off + 1];
        float4 c1 = A[off + 1 + CS4];  float4 e1 = B[off + 1 + CS4];
        float4 c2 = A[off + 1 + 2*CS4];float4 e2 = B[off + 1 + 2*CS4];
        x.x = (a0.x-b0.x)+(a1.x-b1.x)+(a2.x-b2.x);
        x.y = (a0.y-b0.y)+(a1.y-b1.y)+(a2.y-b2.y);
        x.z = (a0.z-b0.z)+(a1.z-b1.z)+(a2.z-b2.z);
        x.w = (a0.w-b0.w)+(a1.w-b1.w)+(a2.w-b2.w);
        y.x = (c0.x-e0.x)+(c1.x-e1.x)+(c2.x-e2.x);
        y.y = (c0.y-e0.y)+(c1.y-e1.y)+(c2.y-e2.y);
        y.z = (c0.z-e0.z)+(c1.z-e1.z)+(c2.z-e2.z);
        y.w = (c0.w-e0.w)+(c1.w-e1.w)+(c2.w-e2.w);
    }
}

__global__ void detail_loss_stream(const float* __restrict__ infer,
                                   const float* __restrict__ ref,
                                   float* __restrict__ out)
{
    const int lane = threadIdx.x;            // 0..31, lane owns cols 8*lane..8*lane+7
    const int task = blockIdx.x;             // one warp per block
    const int n    = task >> 4;              // image
    const int t    = task & 15;              // strip
    const int h0   = t * STRIP;

    const size_t base = (size_t)n * IMG_STRIDE;
    const float4* __restrict__ A = (const float4*)(infer + base);
    const float4* __restrict__ B = (const float4*)(ref   + base);

    float4 px, py, cx, cy, nx, ny;
    load_row(A, B, h0 - 1, lane, px, py);    // halo above (zeros at image top)
    load_row(A, B, h0,     lane, cx, cy);

    float acc = 0.f;
    #pragma unroll 4
    for (int i = 0; i < STRIP; i++) {
        load_row(A, B, h0 + 1 + i, lane, nx, ny);   // row below current

        // horizontal term for current row: |d[w+1] - d[w-1]|, zero-padded in w
        float xm1 = __shfl_up_sync(0xffffffffu, cy.w, 1);
        if (lane == 0) xm1 = 0.f;
        float xp8 = __shfl_down_sync(0xffffffffu, cx.x, 1);
        if (lane == 31) xp8 = 0.f;
        acc += fabsf(cx.y - xm1)  + fabsf(cx.z - cx.x)
             + fabsf(cx.w - cx.y) + fabsf(cy.x - cx.z)
             + fabsf(cy.y - cx.w) + fabsf(cy.z - cy.x)
             + fabsf(cy.w - cy.y) + fabsf(xp8  - cy.z);

        // vertical term for current row: |d[r+1] - d[r-1]|
        acc += fabsf(nx.x - px.x) + fabsf(nx.y - px.y)
             + fabsf(nx.z - px.z) + fabsf(nx.w - px.w)
             + fabsf(ny.x - py.x) + fabsf(ny.y - py.y)
             + fabsf(ny.z - py.z) + fabsf(ny.w - py.w);

        px = cx; py = cy; cx = nx; cy = ny;
    }

    // warp reduction (fixed order -> deterministic)
    #pragma unroll
    for (int o = 16; o > 0; o >>= 1)
        acc += __shfl_xor_sync(0xffffffffu, acc, o);
    if (lane == 0) g_partials[task] = acc;

    // fused final reduction: last-finishing warp sums all partials
    int lastflag = 0;
    if (lane == 0) {
        __threadfence();
        unsigned old = atomicAdd(&g_count, 1u);
        lastflag = (old == NTASK - 1);
        if (lastflag) g_count = 0;           // reset for next graph replay
    }
    lastflag = __shfl_sync(0xffffffffu, lastflag, 0);
    if (lastflag) {
        __threadfence();                      // acquire all partials
        float s = 0.f;
        for (int i = lane; i < NTASK; i += 32) s += g_partials[i];
        #pragma unroll
        for (int o = 16; o > 0; o >>= 1)
            s += __shfl_xor_sync(0xffffffffu, s, o);
        if (lane == 0) {
            // result = A / (4 * 98 * 258 * 256): 0.5 grad coeff folded out,
            // /2 average of the two losses, mean denom 98*258*256 per term.
            out[0] = s * (1.0f / 25890816.0f);
        }
    }
}

extern "C" void kernel_launch(void* const* d_in, const int* in_sizes, int n_in,
                              void* d_out, int out_size)
{
    const float* infer = (const float*)d_in[0];
    const float* ref   = (const float*)d_in[1];
    float* out = (float*)d_out;
    (void)in_sizes; (void)n_in; (void)out_size;

    detail_loss_stream<<<NTASK, 32>>>(infer, ref, out);
}